// round 9
// baseline (speedup 1.0000x reference)
#include <cuda_runtime.h>
#include <math.h>
#include <stdint.h>

#define C_DIM 512
#define CF    256      // cond features
#define NH    8
#define DH    64
#define NTOK  4096     // N*H*W = 4*32*32
#define HH    32
#define WWID  32
#define KSZ   7
#define WIN   49
#define EPSF  1e-6f

// GEMM tiling
#define BK        32
#define AP        36            // A smem row stride (words): bank = 4r+c, conflict-free
#define BP        136           // B smem k-row stride (words): bank = 8c+r, conflict-free
#define A_WORDS   (128 * AP)    // 4608
#define B_WORDS   (BK * BP)     // 4352
#define STG_WORDS (A_WORDS + B_WORDS)
#define NSTAGE    3
#define GEMM_SMEM (NSTAGE * STG_WORDS * 4)   // 107520 bytes
#define EPI_STRIDE 132          // epilogue staging row stride (words)

// attention tiling: 4x4 token tile, window union <= 10x10
#define ATILE     4
#define SPAN      10
#define KVSTRIDE  68            // padded row stride (words) for K/V smem rows
#define ATTN_SMEM ((SPAN * SPAN * KVSTRIDE * 2 + 16 * KVSTRIDE + 16 * 52 + 16) * 4)

// fused norm smem: x tile [512][33] + reductions
#define NORM_SMEM ((C_DIM * 33 + 8 * 33 + 32) * 4)

// ---------------- scratch (static device globals; no allocations) ------------
__device__ float g_s[C_DIM];
__device__ float g_xn[NTOK * C_DIM];          // 8 MB
__device__ float g_qkv[NTOK * 3 * C_DIM];     // 24 MB  (q|k|v each 512 cols)
__device__ float g_o[NTOK * C_DIM];           // 8 MB

// ---------------- s = cond @ norm_w + 1 --------------------------------------
__global__ void nsab_s_kernel(const float* __restrict__ cond,
                              const float* __restrict__ norm_w) {
    int c = blockIdx.x * blockDim.x + threadIdx.x;
    if (c >= C_DIM) return;
    float acc = 1.0f;
#pragma unroll 8
    for (int k = 0; k < CF; k++) acc += cond[k] * norm_w[k * C_DIM + c];
    g_s[c] = acc;
}

// ---------------- fused RMS-norm + transpose (C,tok)->(tok,C) ----------------
__global__ __launch_bounds__(256) void nsab_norm_fused(const float* __restrict__ x) {
    extern __shared__ float smf[];
    float* t    = smf;                       // [512][33]
    float* red  = smf + C_DIM * 33;          // [8][33]
    float* rsh  = red + 8 * 33;              // [32]

    int tok0 = blockIdx.x * 32;
    int tx = threadIdx.x & 31;               // token lane
    int ty = threadIdx.x >> 5;               // 0..7

    float ss = 0.0f;
#pragma unroll 16
    for (int i = 0; i < 64; i++) {
        int c = ty + 8 * i;
        float v = x[(size_t)c * NTOK + tok0 + tx];
        t[c * 33 + tx] = v;
        ss += v * v;
    }
    red[ty * 33 + tx] = ss;
    __syncthreads();
    if (ty == 0) {
        float tot = 0.0f;
#pragma unroll
        for (int j = 0; j < 8; j++) tot += red[j * 33 + tx];
        rsh[tx] = rsqrtf(tot * (1.0f / (float)C_DIM) + EPSF);
    }
    __syncthreads();

#pragma unroll 4
    for (int cc = 0; cc < 16; cc++) {
        int c = cc * 32 + tx;
        float sc = g_s[c];
#pragma unroll
        for (int rr = 0; rr < 4; rr++) {
            int row = ty * 4 + rr;
            g_xn[(size_t)(tok0 + row) * C_DIM + c] = t[c * 33 + row] * sc * rsh[row];
        }
    }
}

// ---------------- tf32 tensor-core GEMM, cp.async 3-stage pipeline -----------
// EPI==0 : qkv projection; for q/k col-tiles the epilogue fuses the per-head
//          L2-norm + RoPE (stage acc->smem, warp-reduce, rotate, single STG).
// EPI==1 : C[c*M + r] = acc + skip[c*M + r]   (transpose-back + residual)
__device__ __forceinline__ void cp16(uint32_t dst, const void* src) {
    asm volatile("cp.async.ca.shared.global [%0], [%1], 16;\n"
                 :: "r"(dst), "l"(src));
}
__device__ __forceinline__ void cp_commit() {
    asm volatile("cp.async.commit_group;\n" ::: "memory");
}
__device__ __forceinline__ void cp_wait1() {
    asm volatile("cp.async.wait_group 1;\n" ::: "memory");
}
__device__ __forceinline__ void cp_wait0() {
    asm volatile("cp.async.wait_group 0;\n" ::: "memory");
}

template <int EPI>
__global__ __launch_bounds__(256, 2) void nsab_mma_gemm(
    const float* __restrict__ A, const float* __restrict__ B,
    float* __restrict__ Cmat, const float* __restrict__ skip,
    const float* __restrict__ pos, const float* __restrict__ scale,
    int M, int N, int K) {
    extern __shared__ uint32_t sm[];

    const int tid = threadIdx.x;
    const int brow = blockIdx.y * 128;
    const int bcol = blockIdx.x * 128;

    const int warp = tid >> 5;
    const int lane = tid & 31;
    const int m_warp = (warp >> 2) * 64;
    const int n_warp = (warp & 3) * 32;
    const int r = lane >> 2;            // 0..7
    const int c = lane & 3;             // 0..3

    const int a_row = tid >> 3, a_q = tid & 7;
    const int b_k = tid >> 5, b_q = tid & 31;
    uint32_t smem_base;
    {
        void* p = (void*)sm;
        smem_base = (uint32_t)__cvta_generic_to_shared(p);
    }

    float acc[4][4][4];
#pragma unroll
    for (int mt = 0; mt < 4; mt++)
#pragma unroll
        for (int nt = 0; nt < 4; nt++)
#pragma unroll
            for (int i = 0; i < 4; i++) acc[mt][nt][i] = 0.0f;

    const int KT = K >> 5;

    auto issue = [&](int kt, int s) {
        uint32_t sA = smem_base + (uint32_t)(s * STG_WORDS) * 4u;
        uint32_t sB = sA + A_WORDS * 4u;
#pragma unroll
        for (int i = 0; i < 4; i++) {
            int row = a_row + 32 * i;
            cp16(sA + (uint32_t)(row * AP + a_q * 4) * 4u,
                 A + (size_t)(brow + row) * K + kt * BK + a_q * 4);
        }
#pragma unroll
        for (int i = 0; i < 4; i++) {
            int k = b_k + 8 * i;
            cp16(sB + (uint32_t)(k * BP + b_q * 4) * 4u,
                 B + (size_t)(kt * BK + k) * N + bcol + b_q * 4);
        }
        cp_commit();
    };

    issue(0, 0);
    if (KT > 1) issue(1, 1);

    int stage = 0;
    for (int kt = 0; kt < KT; kt++) {
        if (kt + 1 < KT) cp_wait1(); else cp_wait0();
        __syncthreads();
        if (kt + 2 < KT) {
            int ns = stage + 2; if (ns >= NSTAGE) ns -= NSTAGE;
            issue(kt + 2, ns);
        }

        const uint32_t* Asu = sm + stage * STG_WORDS;
        const uint32_t* Bsu = Asu + A_WORDS;

#pragma unroll
        for (int j = 0; j < 4; j++) {
            uint32_t a[4][4];
#pragma unroll
            for (int mt = 0; mt < 4; mt++) {
                const uint32_t* p0 = Asu + (m_warp + mt * 16 + r) * AP + j * 8 + c;
                a[mt][0] = p0[0];
                a[mt][2] = p0[4];
                a[mt][1] = p0[8 * AP];
                a[mt][3] = p0[8 * AP + 4];
            }
            uint32_t b0[4], b1[4];
#pragma unroll
            for (int nt = 0; nt < 4; nt++) {
                const uint32_t* q0 = Bsu + (j * 8 + c) * BP + n_warp + nt * 8 + r;
                b0[nt] = q0[0];
                b1[nt] = q0[4 * BP];
            }
#pragma unroll
            for (int mt = 0; mt < 4; mt++)
#pragma unroll
                for (int nt = 0; nt < 4; nt++) {
                    asm volatile(
                        "mma.sync.aligned.m16n8k8.row.col.f32.tf32.tf32.f32 "
                        "{%0,%1,%2,%3}, {%4,%5,%6,%7}, {%8,%9}, {%0,%1,%2,%3};"
                        : "+f"(acc[mt][nt][0]), "+f"(acc[mt][nt][1]),
                          "+f"(acc[mt][nt][2]), "+f"(acc[mt][nt][3])
                        : "r"(a[mt][0]), "r"(a[mt][1]),
                          "r"(a[mt][2]), "r"(a[mt][3]),
                          "r"(b0[nt]), "r"(b1[nt]));
                }
        }

        stage++; if (stage >= NSTAGE) stage -= NSTAGE;
    }

    if (EPI == 0 && bcol < 1024) {
        // -------- fused QK-norm + RoPE epilogue (this tile = 2 full heads) ---
        float* S = (float*)sm;               // [128][EPI_STRIDE]
        __syncthreads();                     // all warps done with stage smem
#pragma unroll
        for (int mt = 0; mt < 4; mt++) {
            int row = m_warp + mt * 16 + r;
#pragma unroll
            for (int nt = 0; nt < 4; nt++) {
                int col = n_warp + nt * 8 + 2 * c;
                S[row * EPI_STRIDE + col]           = acc[mt][nt][0];
                S[row * EPI_STRIDE + col + 1]       = acc[mt][nt][1];
                S[(row + 8) * EPI_STRIDE + col]     = acc[mt][nt][2];
                S[(row + 8) * EPI_STRIDE + col + 1] = acc[mt][nt][3];
            }
        }
        __syncthreads();

        // per-lane constants (head depends only on lh; theta index on lane&15)
        int head0 = (bcol >> 6) & 7;
        float ssc0 = sqrtf(scale[head0]);
        float ssc1 = sqrtf(scale[head0 + 1]);
        int i = lane & 15;
        float freq0 = expf(1.1447298858494002f +
                           (float)((i & 7) * 8 + head0) * 0.03597789207803891f);
        float freq1 = expf(1.1447298858494002f +
                           (float)((i & 7) * 8 + head0 + 1) * 0.03597789207803891f);

        // each warp: 32 (token, head) pairs = 16 tokens x 2 heads
#pragma unroll 4
        for (int it = 0; it < 32; it++) {
            int p = warp * 32 + it;
            int tok_l = p >> 1, lh = p & 1;
            float v0 = S[tok_l * EPI_STRIDE + lh * 64 + lane];
            float v1 = S[tok_l * EPI_STRIDE + lh * 64 + 32 + lane];
            float ss = v0 * v0 + v1 * v1;
#pragma unroll
            for (int o = 16; o; o >>= 1) ss += __shfl_xor_sync(0xFFFFFFFFu, ss, o);
            float nrm = (lh ? ssc1 : ssc0) * rsqrtf(ss + EPSF);
            v0 *= nrm; v1 *= nrm;

            int tok = brow + tok_l;
            int hw = tok & 1023;
            float pxy = (i < 8) ? pos[hw * 2] : pos[hw * 2 + 1];
            float th = pxy * (lh ? freq1 : freq0);
            float ct = cosf(th), st = sinf(th);
            float partner = __shfl_xor_sync(0xFFFFFFFFu, v0, 16);
            float vo = (lane < 16) ? (v0 * ct - partner * st)
                                   : (v0 * ct + partner * st);

            float* dst = &Cmat[(size_t)tok * N + bcol + lh * 64 + lane];
            dst[0]  = vo;
            dst[32] = v1;
        }
    } else {
#pragma unroll
        for (int mt = 0; mt < 4; mt++) {
            int row = brow + m_warp + mt * 16 + r;
#pragma unroll
            for (int nt = 0; nt < 4; nt++) {
                int col = bcol + n_warp + nt * 8 + 2 * c;
                if (EPI == 0) {
                    float2 v0 = make_float2(acc[mt][nt][0], acc[mt][nt][1]);
                    float2 v1 = make_float2(acc[mt][nt][2], acc[mt][nt][3]);
                    *(float2*)&Cmat[(size_t)row * N + col] = v0;
                    *(float2*)&Cmat[(size_t)(row + 8) * N + col] = v1;
                } else {
                    size_t i00 = (size_t)col * M + row;
                    size_t i01 = (size_t)(col + 1) * M + row;
                    Cmat[i00] = acc[mt][nt][0] + skip[i00];
                    Cmat[i01] = acc[mt][nt][1] + skip[i01];
                    Cmat[i00 + 8] = acc[mt][nt][2] + skip[i00 + 8];
                    Cmat[i01 + 8] = acc[mt][nt][3] + skip[i01 + 8];
                }
            }
        }
    }
}

// ---------------- tiled 7x7 neighborhood attention ---------------------------
__global__ __launch_bounds__(256) void nsab_attn_kernel() {
    extern __shared__ float sma[];
    float* sk = sma;                                   // [100][KVSTRIDE]
    float* sv = sk + SPAN * SPAN * KVSTRIDE;           // [100][KVSTRIDE]
    float* sq = sv + SPAN * SPAN * KVSTRIDE;           // [16][KVSTRIDE]
    float* sl = sq + 16 * KVSTRIDE;                    // [16][52]
    float* pinv = sl + 16 * 52;                        // [16]

    int tid = threadIdx.x;
    int th = blockIdx.x >> 3, tw = blockIdx.x & 7;
    int head = blockIdx.y;
    int n = blockIdx.z;
    int h1 = th * ATILE, w1 = tw * ATILE;

    int h0min = min(max(h1 - 3, 0), HH - KSZ);
    int w0min = min(max(w1 - 3, 0), WWID - KSZ);
    int h0max = min(max(h1 + ATILE - 1 - 3, 0), HH - KSZ);
    int w0max = min(max(w1 + ATILE - 1 - 3, 0), WWID - KSZ);
    int span_h = h0max - h0min + KSZ;    // <= 10
    int span_w = w0max - w0min + KSZ;    // <= 10

    int total = span_h * span_w * 16;
    for (int idxi = tid; idxi < total; idxi += 256) {
        int kpos = idxi >> 4, f = idxi & 15;
        int kr = kpos / span_w, kc = kpos - kr * span_w;
        size_t gbase = (size_t)((n << 10) + (h0min + kr) * 32 + (w0min + kc)) * 1536
                       + head * 64 + f * 4;
        float4 kvv = *(const float4*)&g_qkv[gbase + 512];
        float4 vvv = *(const float4*)&g_qkv[gbase + 1024];
        *(float4*)&sk[kpos * KVSTRIDE + f * 4] = kvv;
        *(float4*)&sv[kpos * KVSTRIDE + f * 4] = vvv;
    }
    {
        int tl = tid >> 4, f = tid & 15;
        int hh = h1 + (tl >> 2), ww = w1 + (tl & 3);
        size_t gbase = (size_t)((n << 10) + hh * 32 + ww) * 1536 + head * 64 + f * 4;
        *(float4*)&sq[tl * KVSTRIDE + f * 4] = *(const float4*)&g_qkv[gbase];
    }
    __syncthreads();

    for (int it = tid; it < 16 * WIN; it += 256) {
        int tl = it / WIN, wp = it - tl * WIN;
        int hh = h1 + (tl >> 2), ww = w1 + (tl & 3);
        int dh0 = min(max(hh - 3, 0), HH - KSZ) - h0min;
        int dw0 = min(max(ww - 3, 0), WWID - KSZ) - w0min;
        int kr = wp / KSZ, kc = wp - kr * KSZ;
        const float4* kv = (const float4*)&sk[((dh0 + kr) * span_w + dw0 + kc) * KVSTRIDE];
        const float4* qv = (const float4*)&sq[tl * KVSTRIDE];
        float acc = 0.0f;
#pragma unroll
        for (int i = 0; i < 16; i++) {
            float4 a = kv[i], b = qv[i];
            acc += a.x * b.x + a.y * b.y + a.z * b.z + a.w * b.w;
        }
        sl[tl * 52 + wp] = acc;
    }
    __syncthreads();

    if (tid < 16) {
        float mx = -1e30f;
#pragma unroll
        for (int j = 0; j < WIN; j++) mx = fmaxf(mx, sl[tid * 52 + j]);
        float den = 0.0f;
#pragma unroll
        for (int j = 0; j < WIN; j++) {
            float e = __expf(sl[tid * 52 + j] - mx);
            sl[tid * 52 + j] = e;
            den += e;
        }
        pinv[tid] = 1.0f / den;
    }
    __syncthreads();

    for (int idxo = tid; idxo < 16 * 64; idxo += 256) {
        int tl = idxo >> 6, e = idxo & 63;
        int hh = h1 + (tl >> 2), ww = w1 + (tl & 3);
        int dh0 = min(max(hh - 3, 0), HH - KSZ) - h0min;
        int dw0 = min(max(ww - 3, 0), WWID - KSZ) - w0min;
        float acc = 0.0f;
#pragma unroll
        for (int kr = 0; kr < KSZ; kr++) {
            int base = (dh0 + kr) * span_w + dw0;
#pragma unroll
            for (int kc = 0; kc < KSZ; kc++) {
                acc += sl[tl * 52 + kr * KSZ + kc] * sv[(base + kc) * KVSTRIDE + e];
            }
        }
        g_o[(size_t)((n << 10) + hh * 32 + ww) * 512 + head * 64 + e] = acc * pinv[tl];
    }
}

// ---------------- launch ------------------------------------------------------
extern "C" void kernel_launch(void* const* d_in, const int* in_sizes, int n_in,
                              void* d_out, int out_size) {
    const float* x      = (const float*)d_in[0];
    const float* pos    = (const float*)d_in[1];
    const float* cond   = (const float*)d_in[2];
    const float* norm_w = (const float*)d_in[3];
    const float* qkv_w  = (const float*)d_in[4];
    const float* scale  = (const float*)d_in[5];
    const float* out_w  = (const float*)d_in[6];
    float* out = (float*)d_out;

    float *p_xn, *p_qkv, *p_o;
    cudaGetSymbolAddress((void**)&p_xn,  g_xn);
    cudaGetSymbolAddress((void**)&p_qkv, g_qkv);
    cudaGetSymbolAddress((void**)&p_o,   g_o);

    cudaFuncSetAttribute(nsab_mma_gemm<0>,
                         cudaFuncAttributeMaxDynamicSharedMemorySize, GEMM_SMEM);
    cudaFuncSetAttribute(nsab_mma_gemm<1>,
                         cudaFuncAttributeMaxDynamicSharedMemorySize, GEMM_SMEM);
    cudaFuncSetAttribute(nsab_attn_kernel,
                         cudaFuncAttributeMaxDynamicSharedMemorySize, ATTN_SMEM);
    cudaFuncSetAttribute(nsab_norm_fused,
                         cudaFuncAttributeMaxDynamicSharedMemorySize, NORM_SMEM);

    nsab_s_kernel<<<2, 256>>>(cond, norm_w);
    nsab_norm_fused<<<NTOK / 32, 256, NORM_SMEM>>>(x);
    nsab_mma_gemm<0><<<dim3(3 * C_DIM / 128, NTOK / 128), 256, GEMM_SMEM>>>(
        p_xn, qkv_w, p_qkv, nullptr, pos, scale, NTOK, 3 * C_DIM, C_DIM);
    nsab_attn_kernel<<<dim3(64, NH, 4), 256, ATTN_SMEM>>>();
    nsab_mma_gemm<1><<<dim3(C_DIM / 128, NTOK / 128), 256, GEMM_SMEM>>>(
        p_o, out_w, out, x, nullptr, nullptr, NTOK, C_DIM, C_DIM);
}